// round 12
// baseline (speedup 1.0000x reference)
#include <cuda_runtime.h>
#include <cstdint>

// Problem constants
#define BB 4
#define SS 2048
#define DD 512
#define HH 8
#define HD 64
#define MROWS (BB*SS)   // 8192

// Scratch (static device arrays -- allocation-free per harness rules)
__device__ float g_gate[BB*SS*DD];       // [b,s,d]
__device__ float g_q[BB*HH*SS*HD];       // [b,h,s,d]
__device__ float g_k[BB*HH*SS*HD];
__device__ float g_v[BB*HH*SS*HD];
__device__ float g_o[BB*SS*DD];          // [b,s,d]
__device__ float g_ng[BB*SS*DD];         // layernorm(o) * gate

__device__ __forceinline__ float silu_f(float x) {
    return __fdividef(x, 1.0f + __expf(-x));
}
__device__ __forceinline__ uint32_t f2tf(float x) {
    uint32_t r; asm("cvt.rna.tf32.f32 %0, %1;" : "=r"(r) : "f"(x)); return r;
}
// D = A(16x8,row) * B(8x8,col) + D, tf32 in, f32 accum
__device__ __forceinline__ void mma_tf32(float* c, const uint32_t* a, const uint32_t* b) {
    asm volatile(
        "mma.sync.aligned.m16n8k8.row.col.f32.tf32.tf32.f32 "
        "{%0,%1,%2,%3}, {%4,%5,%6,%7}, {%8,%9}, {%0,%1,%2,%3};"
        : "+f"(c[0]), "+f"(c[1]), "+f"(c[2]), "+f"(c[3])
        : "r"(a[0]), "r"(a[1]), "r"(a[2]), "r"(a[3]), "r"(b[0]), "r"(b[1]));
}

// ---------------------------------------------------------------------------
// tf32 mma.sync GEMM: C[M,N] = A[M,512] @ W[N,512]^T (+bias, +epilogue)
// CTA: 128x128 tile, 256 threads = 8 warps (2 M x 4 N), warp = 64x32.
// Smem DOUBLE-BUFFERED K-blocks: per iteration LDG(next)->MMA(cur)->
// STS(next->other stage)->one __syncthreads. STS overlaps other warps' MMA.
// MODE 0: A = x,    epilogue = silu(.)+scatter to gate/q/k/v  (N = 2048)
// MODE 1: A = g_ng, epilogue = +b2 -> out                     (N = 512)
// ---------------------------------------------------------------------------
#define KST 36
template<int MODE>
__global__ void __launch_bounds__(256, 2) tc_gemm(
    const float* __restrict__ A_in,
    const float* __restrict__ W,
    const float* __restrict__ bias,
    float* __restrict__ out)
{
    extern __shared__ uint32_t gsm[];
    uint32_t* As = gsm;                  // [2][128][KST] tf32 bits
    uint32_t* Bs = gsm + 2 * 128 * KST;  // [2][128][KST]

    const float* A = (MODE == 0) ? A_in : g_ng;
    const int tid  = threadIdx.x;
    const int wid  = tid >> 5;
    const int lane = tid & 31;
    const int g    = lane >> 2;
    const int t    = lane & 3;
    const int row0 = blockIdx.y * 128;
    const int col0 = blockIdx.x * 128;
    const int wm   = (wid >> 2) * 64;
    const int wn   = (wid & 3) * 32;

    const int lr  = tid >> 3;            // 0..31: row pair base
    const int lc4 = (tid & 7) << 2;      // 0..28: k offset

    float acc[4][4][4];
    #pragma unroll
    for (int i = 0; i < 4; i++)
        #pragma unroll
        for (int j = 0; j < 4; j++)
            #pragma unroll
            for (int q = 0; q < 4; q++) acc[i][j][q] = 0.0f;

    // prefetch + store K-block 0 into stage 0
    float4 pa[4], pb[4];
    #pragma unroll
    for (int l = 0; l < 4; l++) {
        const int r = lr + l * 32;
        pa[l] = *(const float4*)&A[(size_t)(row0 + r) * 512 + lc4];
        pb[l] = *(const float4*)&W[(size_t)(col0 + r) * 512 + lc4];
    }
    #pragma unroll
    for (int l = 0; l < 4; l++) {
        const int r = lr + l * 32;
        *(uint4*)&As[r * KST + lc4] =
            make_uint4(f2tf(pa[l].x), f2tf(pa[l].y), f2tf(pa[l].z), f2tf(pa[l].w));
        *(uint4*)&Bs[r * KST + lc4] =
            make_uint4(f2tf(pb[l].x), f2tf(pb[l].y), f2tf(pb[l].z), f2tf(pb[l].w));
    }
    __syncthreads();

    for (int kb = 0; kb < 16; kb++) {
        const uint32_t* Ac = As + (kb & 1) * 128 * KST;
        const uint32_t* Bc = Bs + (kb & 1) * 128 * KST;

        // issue LDG for next block; consumed by STS after the MMA loop
        if (kb < 15) {
            const int k0 = (kb + 1) * 32;
            #pragma unroll
            for (int l = 0; l < 4; l++) {
                const int r = lr + l * 32;
                pa[l] = *(const float4*)&A[(size_t)(row0 + r) * 512 + k0 + lc4];
                pb[l] = *(const float4*)&W[(size_t)(col0 + r) * 512 + k0 + lc4];
            }
        }

        #pragma unroll
        for (int k8 = 0; k8 < 4; k8++) {
            const int kk = k8 * 8;
            uint32_t af[4][4];
            #pragma unroll
            for (int mt = 0; mt < 4; mt++) {
                const int mr = wm + mt * 16 + g;
                af[mt][0] = Ac[mr * KST + kk + t];
                af[mt][1] = Ac[(mr + 8) * KST + kk + t];
                af[mt][2] = Ac[mr * KST + kk + t + 4];
                af[mt][3] = Ac[(mr + 8) * KST + kk + t + 4];
            }
            uint32_t bf[4][2];
            #pragma unroll
            for (int nt = 0; nt < 4; nt++) {
                const int nr = wn + nt * 8 + g;
                bf[nt][0] = Bc[nr * KST + kk + t];
                bf[nt][1] = Bc[nr * KST + kk + t + 4];
            }
            #pragma unroll
            for (int mt = 0; mt < 4; mt++)
                #pragma unroll
                for (int nt = 0; nt < 4; nt++)
                    mma_tf32(acc[mt][nt], af[mt], bf[nt]);
        }

        // store next block into the other stage (overlaps other warps' MMA)
        if (kb < 15) {
            uint32_t* An = As + ((kb + 1) & 1) * 128 * KST;
            uint32_t* Bn = Bs + ((kb + 1) & 1) * 128 * KST;
            #pragma unroll
            for (int l = 0; l < 4; l++) {
                const int r = lr + l * 32;
                *(uint4*)&An[r * KST + lc4] =
                    make_uint4(f2tf(pa[l].x), f2tf(pa[l].y), f2tf(pa[l].z), f2tf(pa[l].w));
                *(uint4*)&Bn[r * KST + lc4] =
                    make_uint4(f2tf(pb[l].x), f2tf(pb[l].y), f2tf(pb[l].z), f2tf(pb[l].w));
            }
        }
        __syncthreads();
    }

    #pragma unroll
    for (int mt = 0; mt < 4; mt++) {
        #pragma unroll
        for (int half = 0; half < 2; half++) {
            const int r = row0 + wm + mt * 16 + g + half * 8;
            const int b = r >> 11;
            const int s = r & 2047;
            #pragma unroll
            for (int nt = 0; nt < 4; nt++) {
                const int j = col0 + wn + nt * 8 + 2 * t;
                float2 v;
                v.x = acc[mt][nt][half * 2 + 0] + __ldg(&bias[j]);
                v.y = acc[mt][nt][half * 2 + 1] + __ldg(&bias[j + 1]);
                if (MODE == 0) {
                    v.x = silu_f(v.x);
                    v.y = silu_f(v.y);
                    const int c   = j >> 9;
                    const int rem = j & 511;
                    if (c == 0) {
                        *(float2*)&g_gate[(size_t)r * 512 + rem] = v;
                    } else {
                        const int head = rem >> 6;
                        const int d    = rem & 63;
                        float* dst = (c == 1) ? g_q : ((c == 2) ? g_k : g_v);
                        *(float2*)&dst[((size_t)(b * 8 + head) * 2048 + s) * 64 + d] = v;
                    }
                } else {
                    *(float2*)&out[(size_t)r * 512 + j] = v;
                }
            }
        }
    }
}

// ---------------------------------------------------------------------------
// Causal HSTU attention on tf32 mma.sync.
// Block: 256 thr = 8 warps, 128-query tile. Warp layout 8M x 1N: each warp
// owns 16 query rows and the FULL 64-key / 64-dim width. Its GEMM1 output
// rows (St) are exactly the A-operand rows of its GEMM2 -> the inter-GEMM
// block barrier becomes a warp-local __syncwarp. Register prefetch of next
// K/V tile overlaps LDG latency with the MMA loops.
// ---------------------------------------------------------------------------
#define AQST 68   // smem word stride; 68 mod 32 = 4 -> conflict-free frags

__global__ void __launch_bounds__(256, 2) attn_mma_kernel() {
    extern __shared__ uint32_t smw[];
    uint32_t* Qs = smw;                  // [128][AQST] tf32 [query][dim]
    uint32_t* Ks = smw + 128 * AQST;     // [64][AQST]  tf32 [key][dim]
    uint32_t* Vt = smw + 192 * AQST;     // [64][AQST]  tf32 [dim][key]
    uint32_t* St = smw + 256 * AQST;     // [128][AQST] tf32 [query][key]

    const int tid  = threadIdx.x;
    const int wid  = tid >> 5;
    const int lane = tid & 31;
    const int g    = lane >> 2;
    const int t    = lane & 3;
    const int qt   = blockIdx.x;         // 0..15 (128-query tiles)
    const int bh   = blockIdx.y;
    const int b    = bh >> 3;
    const int h    = bh & 7;
    const size_t base = (size_t)bh * SS * HD;
    const float* qp = g_q + base;
    const float* kp = g_k + base;
    const float* vp = g_v + base;
    const int s0 = qt * 128;
    const int wm = wid * 16;             // warp query offset: 0..112

    // Stage Q (128 x 64, tf32)
    #pragma unroll
    for (int l = 0; l < 8; l++) {
        const int idx = tid + l * 256;
        const int r   = idx >> 4;
        const int c4  = (idx & 15) << 2;
        float4 qv = *(const float4*)&qp[(size_t)(s0 + r) * 64 + c4];
        *(uint4*)&Qs[r * AQST + c4] =
            make_uint4(f2tf(qv.x), f2tf(qv.y), f2tf(qv.z), f2tf(qv.w));
    }

    float oacc[8][4];
    #pragma unroll
    for (int i = 0; i < 8; i++)
        #pragma unroll
        for (int j = 0; j < 4; j++) oacc[i][j] = 0.0f;

    const int last = 2 * qt + 1;

    // prefetch K/V tile 0
    float4 pk[4], pv[4];
    #pragma unroll
    for (int l = 0; l < 4; l++) {
        const int idx = tid + l * 256;
        const int r   = idx >> 4;
        const int c4  = (idx & 15) << 2;
        pk[l] = *(const float4*)&kp[(size_t)r * 64 + c4];
        pv[l] = *(const float4*)&vp[(size_t)r * 64 + c4];
    }

    for (int kt = 0; kt <= last; kt++) {
        const int t0 = kt * 64;
        __syncthreads();   // prev-iter Ks/Vt reads done (and Qs staged, kt=0)

        // store prefetched K ([key][dim]) and V transposed ([dim][key])
        #pragma unroll
        for (int l = 0; l < 4; l++) {
            const int idx = tid + l * 256;
            const int r   = idx >> 4;
            const int c4  = (idx & 15) << 2;
            *(uint4*)&Ks[r * AQST + c4] =
                make_uint4(f2tf(pk[l].x), f2tf(pk[l].y), f2tf(pk[l].z), f2tf(pk[l].w));
            Vt[(c4 + 0) * AQST + r] = f2tf(pv[l].x);
            Vt[(c4 + 1) * AQST + r] = f2tf(pv[l].y);
            Vt[(c4 + 2) * AQST + r] = f2tf(pv[l].z);
            Vt[(c4 + 3) * AQST + r] = f2tf(pv[l].w);
        }
        __syncthreads();

        // prefetch next K/V tile; latency hides under the MMA loops
        if (kt < last) {
            const int tn = (kt + 1) * 64;
            #pragma unroll
            for (int l = 0; l < 4; l++) {
                const int idx = tid + l * 256;
                const int r   = idx >> 4;
                const int c4  = (idx & 15) << 2;
                pk[l] = *(const float4*)&kp[(size_t)(tn + r) * 64 + c4];
                pv[l] = *(const float4*)&vp[(size_t)(tn + r) * 64 + c4];
            }
        }

        // ---- GEMM 1: scores = Q @ K^T (per warp: M=16 queries, N=64 keys)
        float sacc[8][4];
        #pragma unroll
        for (int i = 0; i < 8; i++)
            #pragma unroll
            for (int j = 0; j < 4; j++) sacc[i][j] = 0.0f;

        #pragma unroll
        for (int k8 = 0; k8 < 8; k8++) {
            const int kk = k8 * 8;
            uint32_t af[4];
            const int mr = wm + g;
            af[0] = Qs[mr * AQST + kk + t];
            af[1] = Qs[(mr + 8) * AQST + kk + t];
            af[2] = Qs[mr * AQST + kk + t + 4];
            af[3] = Qs[(mr + 8) * AQST + kk + t + 4];
            #pragma unroll
            for (int nt = 0; nt < 8; nt++) {
                const int nr = nt * 8 + g;
                uint32_t bf[2];
                bf[0] = Ks[nr * AQST + kk + t];
                bf[1] = Ks[nr * AQST + kk + t + 4];
                mma_tf32(sacc[nt], af, bf);
            }
        }

        // silu + causal mask, re-round to tf32 into warp-private St rows
        const bool diag = (kt >= 2 * qt);
        #pragma unroll
        for (int nt = 0; nt < 8; nt++) {
            const int klocal = nt * 8 + 2 * t;
            const int key    = t0 + klocal;
            #pragma unroll
            for (int half = 0; half < 2; half++) {
                const int qlocal = wm + g + half * 8;
                const int qrow   = s0 + qlocal;
                float v0 = silu_f(sacc[nt][half * 2 + 0] * 0.125f);
                float v1 = silu_f(sacc[nt][half * 2 + 1] * 0.125f);
                if (diag) {
                    if (key     > qrow) v0 = 0.0f;
                    if (key + 1 > qrow) v1 = 0.0f;
                }
                *(uint2*)&St[qlocal * AQST + klocal] =
                    make_uint2(f2tf(v0), f2tf(v1));
            }
        }
        __syncwarp();   // warp-private St: no block barrier needed

        // ---- GEMM 2: O += St @ V  (A=St [query][key], B=Vt [dim][key])
        #pragma unroll
        for (int k8 = 0; k8 < 8; k8++) {
            const int kk = k8 * 8;
            uint32_t af[4];
            const int mr = wm + g;
            af[0] = St[mr * AQST + kk + t];
            af[1] = St[(mr + 8) * AQST + kk + t];
            af[2] = St[mr * AQST + kk + t + 4];
            af[3] = St[(mr + 8) * AQST + kk + t + 4];
            #pragma unroll
            for (int nt = 0; nt < 8; nt++) {
                const int nr = nt * 8 + g;
                uint32_t bf[2];
                bf[0] = Vt[nr * AQST + kk + t];
                bf[1] = Vt[nr * AQST + kk + t + 4];
                mma_tf32(oacc[nt], af, bf);
            }
        }
    }

    // Write O in [b, s, h*64+dim] layout
    #pragma unroll
    for (int nt = 0; nt < 8; nt++) {
        const int dim = nt * 8 + 2 * t;
        #pragma unroll
        for (int half = 0; half < 2; half++) {
            const int srow = s0 + wm + g + half * 8;
            float2 ov = make_float2(oacc[nt][half * 2 + 0], oacc[nt][half * 2 + 1]);
            *(float2*)&g_o[((size_t)(b * SS + srow)) * DD + h * 64 + dim] = ov;
        }
    }
}

// ---------------------------------------------------------------------------
// LayerNorm(o) * gate  -> g_ng
// ---------------------------------------------------------------------------
__global__ void __launch_bounds__(128) ln_gate_kernel(
    const float* __restrict__ lng, const float* __restrict__ lnb)
{
    const int row = blockIdx.x;
    const int tid = threadIdx.x;
    const float* op = g_o + (size_t)row * DD;

    float4 x = *(const float4*)&op[tid * 4];
    float s = x.x + x.y + x.z + x.w;

    const int lane = tid & 31, wid = tid >> 5;
    __shared__ float r1[4], r2[4];

    #pragma unroll
    for (int off = 16; off; off >>= 1) s += __shfl_xor_sync(0xffffffffu, s, off);
    if (lane == 0) r1[wid] = s;
    __syncthreads();
    const float m = (r1[0] + r1[1] + r1[2] + r1[3]) * (1.0f / 512.0f);

    const float dx = x.x - m, dy = x.y - m, dz = x.z - m, dw = x.w - m;
    float sq = dx * dx + dy * dy + dz * dz + dw * dw;
    #pragma unroll
    for (int off = 16; off; off >>= 1) sq += __shfl_xor_sync(0xffffffffu, sq, off);
    if (lane == 0) r2[wid] = sq;
    __syncthreads();
    const float var = (r2[0] + r2[1] + r2[2] + r2[3]) * (1.0f / 512.0f);
    const float inv = rsqrtf(var + 1e-5f);

    float4 gv = *(const float4*)&lng[tid * 4];
    float4 bv = *(const float4*)&lnb[tid * 4];
    float4 gg = *(const float4*)&g_gate[(size_t)row * DD + tid * 4];
    float4 o;
    o.x = (dx * inv * gv.x + bv.x) * gg.x;
    o.y = (dy * inv * gv.y + bv.y) * gg.y;
    o.z = (dz * inv * gv.z + bv.z) * gg.z;
    o.w = (dw * inv * gv.w + bv.w) * gg.w;
    *(float4*)&g_ng[(size_t)row * DD + tid * 4] = o;
}

// ---------------------------------------------------------------------------
extern "C" void kernel_launch(void* const* d_in, const int* in_sizes, int n_in,
                              void* d_out, int out_size) {
    const float* x   = (const float*)d_in[0];
    const float* W1  = (const float*)d_in[1];
    const float* b1  = (const float*)d_in[2];
    const float* lng = (const float*)d_in[3];
    const float* lnb = (const float*)d_in[4];
    const float* W2  = (const float*)d_in[5];
    const float* b2  = (const float*)d_in[6];
    float* out = (float*)d_out;

    const int gemm_smem = 4 * 128 * KST * (int)sizeof(uint32_t);   // 73728 B
    cudaFuncSetAttribute(tc_gemm<0>, cudaFuncAttributeMaxDynamicSharedMemorySize,
                         gemm_smem);
    cudaFuncSetAttribute(tc_gemm<1>, cudaFuncAttributeMaxDynamicSharedMemorySize,
                         gemm_smem);
    const int attn_smem = 384 * AQST * (int)sizeof(uint32_t);      // 104448 B
    cudaFuncSetAttribute(attn_mma_kernel,
                         cudaFuncAttributeMaxDynamicSharedMemorySize, attn_smem);

    // 1) h = silu(x @ W1^T + b1), scattered to gate/q/k/v   (tf32 mma.sync)
    tc_gemm<0><<<dim3(2048 / 128, MROWS / 128), 256, gemm_smem>>>(x, W1, b1, out);

    // 2) causal silu-attention -> g_o [b,s,d]               (tf32 mma.sync)
    attn_mma_kernel<<<dim3(SS / 128, BB * HH), 256, attn_smem>>>();

    // 3) layernorm(o) * gate -> g_ng
    ln_gate_kernel<<<MROWS, 128>>>(lng, lnb);

    // 4) out = g_ng @ W2^T + b2                             (tf32 mma.sync)
    tc_gemm<1><<<dim3(512 / 128, MROWS / 128), 256, gemm_smem>>>(nullptr, W2, b2, out);
}